// round 1
// baseline (speedup 1.0000x reference)
#include <cuda_runtime.h>

// ---------------- problem constants ----------------
namespace {
constexpr int kN0 = 1000000;
constexpr int kN1 = 67584;
constexpr int kN2 = 6144;
constexpr int kN3 = 1024;
constexpr int kFIN = 100;
constexpr int kHID = 256;
constexpr int kOUT = 47;
constexpr int kFAN1 = 15;
constexpr int kFAN2 = 10;
constexpr int kFAN3 = 5;
}  // namespace

// ---------------- scratch (device globals; no allocation allowed) ----------
__device__ float g_A1[(size_t)kN1 * 200];    // [agg1 | x_dst]   54 MB
__device__ float g_h1[(size_t)kN1 * kHID];   // relu layer1 out  69 MB
__device__ float g_A2[(size_t)kN2 * 512];    // [agg2 | h1_dst]  12.6 MB
__device__ float g_h2[(size_t)kN2 * kHID];   //                  6.3 MB
__device__ float g_A3[(size_t)kN3 * 512];    // [agg3 | h2_dst]  2 MB
__device__ float g_W1[200 * kHID];           // [W_l1 ; W_r1]
__device__ float g_W2[512 * kHID];           // [W_l2 ; W_r2]
__device__ float g_W3[512 * kOUT];           // [W_l3 ; W_r3]
__device__ int   g_is64;                     // index dtype flag (1 = int64)

// ---------------- weight packing + index-dtype detection --------------------
__global__ void pack_weights(const float* __restrict__ Wl1, const float* __restrict__ Wr1,
                             const float* __restrict__ Wl2, const float* __restrict__ Wr2,
                             const float* __restrict__ Wl3, const float* __restrict__ Wr3,
                             const void* __restrict__ dst1) {
    int i = blockIdx.x * blockDim.x + threadIdx.x;
    if (i == 0) {
        // dst1 = repeat(arange(N1), 15). Under an int64 interpretation,
        // element 15 == 1. If the data is really int32, the int64 read of
        // element 15 combines int32 elems {30,31} = 2 | (2<<32) != 1.
        g_is64 = (((const long long*)dst1)[15] == 1LL) ? 1 : 0;
    }
    if (i < 200 * kHID) {  // W1 pack
        int k = i >> 8, n = i & 255;
        g_W1[i] = (k < kFIN) ? Wl1[k * kHID + n] : Wr1[(k - kFIN) * kHID + n];
    }
    if (i < 512 * kHID) {  // W2 pack
        int k = i >> 8, n = i & 255;
        g_W2[i] = (k < kHID) ? Wl2[k * kHID + n] : Wr2[(k - kHID) * kHID + n];
    }
    if (i < 512 * kOUT) {  // W3 pack
        int k = i / kOUT, n = i % kOUT;
        g_W3[i] = (k < kHID) ? Wl3[k * kOUT + n] : Wr3[(k - kHID) * kOUT + n];
    }
}

__device__ __forceinline__ long long load_index(const void* p, long long i, int is64) {
    return is64 ? ((const long long*)p)[i] : (long long)((const int*)p)[i];
}

// ---------------- layer-1 aggregation: one warp per dst node ---------------
// Builds A1[i] = [ (1/15) * sum_j x[src1[15i+j]]  |  x[i] ]   (200 floats)
__global__ void agg1_kernel(const float* __restrict__ x, const void* __restrict__ src) {
    int gw = (blockIdx.x * blockDim.x + threadIdx.x) >> 5;
    int lane = threadIdx.x & 31;
    if (gw >= kN1) return;
    const int is64 = g_is64;

    long long myidx = 0;
    if (lane < kFAN1) myidx = load_index(src, (long long)gw * kFAN1 + lane, is64);

    float a0 = 0.f, a1 = 0.f, a2 = 0.f, a3 = 0.f;
#pragma unroll
    for (int j = 0; j < kFAN1; ++j) {
        long long r = __shfl_sync(0xffffffffu, myidx, j);
        const float* xr = x + r * kFIN;
        a0 += xr[lane];
        a1 += xr[lane + 32];
        a2 += xr[lane + 64];
        if (lane < kFIN - 96) a3 += xr[lane + 96];
    }
    const float inv = 1.0f / (float)kFAN1;
    float* o = g_A1 + (long long)gw * 200;
    o[lane]      = a0 * inv;
    o[lane + 32] = a1 * inv;
    o[lane + 64] = a2 * inv;
    if (lane < 4) o[lane + 96] = a3 * inv;
    const float* xd = x + (long long)gw * kFIN;
    o[100 + lane] = xd[lane];
    o[132 + lane] = xd[lane + 32];
    o[164 + lane] = xd[lane + 64];
    if (lane < 4) o[196 + lane] = xd[lane + 96];
}

// ---------------- 256-wide aggregation (layers 2,3): one warp per dst ------
template <int FAN>
__global__ void agg256_kernel(const float* __restrict__ h, const void* __restrict__ src,
                              float* __restrict__ A, int ndst) {
    int gw = (blockIdx.x * blockDim.x + threadIdx.x) >> 5;
    int lane = threadIdx.x & 31;
    if (gw >= ndst) return;
    const int is64 = g_is64;

    long long myidx = 0;
    if (lane < FAN) myidx = load_index(src, (long long)gw * FAN + lane, is64);

    float acc[8];
#pragma unroll
    for (int t = 0; t < 8; ++t) acc[t] = 0.f;

#pragma unroll
    for (int j = 0; j < FAN; ++j) {
        long long r = __shfl_sync(0xffffffffu, myidx, j);
        const float* hr = h + r * kHID;
#pragma unroll
        for (int t = 0; t < 8; ++t) acc[t] += hr[lane + t * 32];
    }
    const float inv = 1.0f / (float)FAN;
    float* o = A + (long long)gw * 512;
#pragma unroll
    for (int t = 0; t < 8; ++t) o[lane + t * 32] = acc[t] * inv;
    const float* hd = h + (long long)gw * kHID;
#pragma unroll
    for (int t = 0; t < 8; ++t) o[256 + lane + t * 32] = hd[lane + t * 32];
}

// ---------------- tiled fp32 GEMM: C = A @ W + bias (opt relu) -------------
// BM=BN=64, BK=16, 256 threads, 4x4 per-thread microtile. M must be %64.
template <bool RELU>
__global__ void gemm_kernel(const float* __restrict__ A, const float* __restrict__ W,
                            const float* __restrict__ bias, float* __restrict__ C,
                            int M, int N, int K) {
    __shared__ float As[16][64];
    __shared__ float Ws[16][64];

    int tid = threadIdx.x;
    int tr = tid >> 4;        // 0..15
    int tc = tid & 15;        // 0..15
    int rowBase = blockIdx.y * 64;
    int colBase = blockIdx.x * 64;

    float acc[4][4];
#pragma unroll
    for (int i = 0; i < 4; ++i)
#pragma unroll
        for (int j = 0; j < 4; ++j) acc[i][j] = 0.f;

    for (int k0 = 0; k0 < K; k0 += 16) {
        // load A tile (64 rows x 16 k), store transposed As[k][row]
#pragma unroll
        for (int i = 0; i < 4; ++i) {
            int e = tid + i * 256;
            int r = e >> 4, c = e & 15;
            int gk = k0 + c;
            float v = 0.f;
            if (gk < K) v = A[(long long)(rowBase + r) * K + gk];
            As[c][r] = v;
        }
        // load W tile (16 k x 64 cols)
#pragma unroll
        for (int i = 0; i < 4; ++i) {
            int e = tid + i * 256;
            int r = e >> 6, c = e & 63;
            int gk = k0 + r, gc = colBase + c;
            float v = 0.f;
            if (gk < K && gc < N) v = W[(long long)gk * N + gc];
            Ws[r][c] = v;
        }
        __syncthreads();
#pragma unroll
        for (int k = 0; k < 16; ++k) {
            float a[4], b[4];
#pragma unroll
            for (int i = 0; i < 4; ++i) a[i] = As[k][tr * 4 + i];
#pragma unroll
            for (int j = 0; j < 4; ++j) b[j] = Ws[k][tc * 4 + j];
#pragma unroll
            for (int i = 0; i < 4; ++i)
#pragma unroll
                for (int j = 0; j < 4; ++j) acc[i][j] = fmaf(a[i], b[j], acc[i][j]);
        }
        __syncthreads();
    }
#pragma unroll
    for (int i = 0; i < 4; ++i) {
        int r = rowBase + tr * 4 + i;
#pragma unroll
        for (int j = 0; j < 4; ++j) {
            int c = colBase + tc * 4 + j;
            if (c < N) {
                float v = acc[i][j] + bias[c];
                if (RELU) v = fmaxf(v, 0.f);
                C[(long long)r * N + c] = v;
            }
        }
    }
}

// ---------------- log_softmax over 47 cols, one warp per row, in-place -----
__global__ void logsoftmax_kernel(float* __restrict__ out) {
    int gw = (blockIdx.x * blockDim.x + threadIdx.x) >> 5;
    int lane = threadIdx.x & 31;
    if (gw >= kN3) return;
    float* row = out + (long long)gw * kOUT;
    float v0 = (lane < kOUT) ? row[lane] : -1e30f;
    float v1 = (lane + 32 < kOUT) ? row[lane + 32] : -1e30f;
    float m = fmaxf(v0, v1);
#pragma unroll
    for (int o = 16; o; o >>= 1) m = fmaxf(m, __shfl_xor_sync(0xffffffffu, m, o));
    float s = 0.f;
    if (lane < kOUT) s += expf(v0 - m);
    if (lane + 32 < kOUT) s += expf(v1 - m);
#pragma unroll
    for (int o = 16; o; o >>= 1) s += __shfl_xor_sync(0xffffffffu, s, o);
    float lse = m + logf(s);
    if (lane < kOUT) row[lane] = v0 - lse;
    if (lane + 32 < kOUT) row[lane + 32] = v1 - lse;
}

// ---------------- launch ---------------------------------------------------
extern "C" void kernel_launch(void* const* d_in, const int* in_sizes, int n_in,
                              void* d_out, int out_size) {
    const float* x   = (const float*)d_in[0];
    const float* Wl1 = (const float*)d_in[1];
    const float* Wr1 = (const float*)d_in[2];
    const float* b1  = (const float*)d_in[3];
    const float* Wl2 = (const float*)d_in[4];
    const float* Wr2 = (const float*)d_in[5];
    const float* b2  = (const float*)d_in[6];
    const float* Wl3 = (const float*)d_in[7];
    const float* Wr3 = (const float*)d_in[8];
    const float* b3  = (const float*)d_in[9];
    const void*  src1 = d_in[10];
    const void*  dst1 = d_in[11];
    const void*  src2 = d_in[12];
    const void*  src3 = d_in[14];
    float* out = (float*)d_out;

    float *A1, *h1, *A2, *h2, *A3, *W1, *W2, *W3;
    cudaGetSymbolAddress((void**)&A1, g_A1);
    cudaGetSymbolAddress((void**)&h1, g_h1);
    cudaGetSymbolAddress((void**)&A2, g_A2);
    cudaGetSymbolAddress((void**)&h2, g_h2);
    cudaGetSymbolAddress((void**)&A3, g_A3);
    cudaGetSymbolAddress((void**)&W1, g_W1);
    cudaGetSymbolAddress((void**)&W2, g_W2);
    cudaGetSymbolAddress((void**)&W3, g_W3);

    // 1. pack weights + detect index dtype
    pack_weights<<<(512 * kHID + 255) / 256, 256>>>(Wl1, Wr1, Wl2, Wr2, Wl3, Wr3, dst1);

    // 2. layer 1
    agg1_kernel<<<kN1 / 8, 256>>>(x, src1);
    {
        dim3 grid(kHID / 64, kN1 / 64);
        gemm_kernel<true><<<grid, 256>>>(A1, W1, b1, h1, kN1, kHID, 200);
    }

    // 3. layer 2
    agg256_kernel<kFAN2><<<kN2 / 8, 256>>>(h1, src2, A2, kN2);
    {
        dim3 grid(kHID / 64, kN2 / 64);
        gemm_kernel<true><<<grid, 256>>>(A2, W2, b2, h2, kN2, kHID, 512);
    }

    // 4. layer 3 (writes logits straight into d_out)
    agg256_kernel<kFAN3><<<kN3 / 8, 256>>>(h2, src3, A3, kN3);
    {
        dim3 grid(1, kN3 / 64);
        gemm_kernel<false><<<grid, 256>>>(A3, W3, b3, out, kN3, kOUT, 512);
    }

    // 5. log_softmax in place
    logsoftmax_kernel<<<kN3 / 8, 256>>>(out);
}

// round 3
// speedup vs baseline: 1.9468x; 1.9468x over previous
#include <cuda_runtime.h>
#include <cuda_bf16.h>
#include <cstdint>
#include <cstddef>

// ---------------- problem constants ----------------
namespace {
constexpr int kN1 = 67584;
constexpr int kN2 = 6144;
constexpr int kN3 = 1024;
constexpr int kFIN = 100;
constexpr int kHID = 256;
constexpr int kOUT = 47;
constexpr int kFAN1 = 15;
constexpr int kFAN2 = 10;
constexpr int kFAN3 = 5;
constexpr int K1P = 256;   // layer-1 K padded (agg 100 | dst 100 | zeros)
constexpr int K2P = 512;   // layer-2/3 K (agg 256 | dst 256)
}  // namespace

// ---------------- scratch (device globals) ----------------------------------
__device__ __nv_bfloat16 g_A1h[(size_t)kN1 * K1P];
__device__ __nv_bfloat16 g_A1l[(size_t)kN1 * K1P];
__device__ float         g_h1[(size_t)kN1 * kHID];
__device__ __nv_bfloat16 g_A2h[(size_t)kN2 * K2P];
__device__ __nv_bfloat16 g_A2l[(size_t)kN2 * K2P];
__device__ float         g_h2[(size_t)kN2 * kHID];
__device__ __nv_bfloat16 g_A3h[(size_t)kN3 * K2P];
__device__ __nv_bfloat16 g_A3l[(size_t)kN3 * K2P];
__device__ __nv_bfloat16 g_W1t[(size_t)256 * 3 * K1P];  // [N=256][K'=768]
__device__ __nv_bfloat16 g_W2t[(size_t)256 * 3 * K2P];  // [256][1536]
__device__ __nv_bfloat16 g_W3t[(size_t)64  * 3 * K2P];  // [64][1536]
__device__ int g_is64;

// ---------------- PTX helpers ------------------------------------------------
__device__ __forceinline__ uint32_t smem_u32(const void* p) {
    uint32_t a;
    asm("{ .reg .u64 t; cvta.to.shared.u64 t, %1; cvt.u32.u64 %0, t; }" : "=r"(a) : "l"(p));
    return a;
}
__device__ __forceinline__ void cpasync16(uint32_t saddr, const void* g) {
    asm volatile("cp.async.cg.shared.global [%0], [%1], 16;" :: "r"(saddr), "l"(g) : "memory");
}
__device__ __forceinline__ void ldm_x4(uint32_t& r0, uint32_t& r1, uint32_t& r2, uint32_t& r3,
                                       uint32_t addr) {
    asm volatile("ldmatrix.sync.aligned.m8n8.x4.shared.b16 {%0,%1,%2,%3}, [%4];"
                 : "=r"(r0), "=r"(r1), "=r"(r2), "=r"(r3) : "r"(addr));
}
__device__ __forceinline__ void ldm_x2(uint32_t& r0, uint32_t& r1, uint32_t addr) {
    asm volatile("ldmatrix.sync.aligned.m8n8.x2.shared.b16 {%0,%1}, [%2];"
                 : "=r"(r0), "=r"(r1) : "r"(addr));
}
__device__ __forceinline__ void mma16816(float* c, const uint32_t* a, uint32_t b0, uint32_t b1) {
    asm volatile(
        "mma.sync.aligned.m16n8k16.row.col.f32.bf16.bf16.f32 "
        "{%0,%1,%2,%3}, {%4,%5,%6,%7}, {%8,%9}, {%0,%1,%2,%3};"
        : "+f"(c[0]), "+f"(c[1]), "+f"(c[2]), "+f"(c[3])
        : "r"(a[0]), "r"(a[1]), "r"(a[2]), "r"(a[3]), "r"(b0), "r"(b1));
}

// ---------------- bf16 split helpers -----------------------------------------
__device__ __forceinline__ void split_store4(__nv_bfloat16* ph, __nv_bfloat16* pl, float4 f) {
    __nv_bfloat162 h01, h23, l01, l23;
    h01.x = __float2bfloat16(f.x); h01.y = __float2bfloat16(f.y);
    h23.x = __float2bfloat16(f.z); h23.y = __float2bfloat16(f.w);
    l01.x = __float2bfloat16(f.x - __bfloat162float(h01.x));
    l01.y = __float2bfloat16(f.y - __bfloat162float(h01.y));
    l23.x = __float2bfloat16(f.z - __bfloat162float(h23.x));
    l23.y = __float2bfloat16(f.w - __bfloat162float(h23.y));
    *(__nv_bfloat162*)ph       = h01;
    *(__nv_bfloat162*)(ph + 2) = h23;
    *(__nv_bfloat162*)pl       = l01;
    *(__nv_bfloat162*)(pl + 2) = l23;
}
__device__ __forceinline__ long long load_index(const void* p, long long i, int is64) {
    return is64 ? ((const long long*)p)[i] : (long long)((const int*)p)[i];
}

// ---------------- pack weights (bf16x3 K-extended, transposed) ---------------
__global__ void pack_weights(const float* __restrict__ Wl1, const float* __restrict__ Wr1,
                             const float* __restrict__ Wl2, const float* __restrict__ Wr2,
                             const float* __restrict__ Wl3, const float* __restrict__ Wr3,
                             const void* __restrict__ dst1) {
    long long i = (long long)blockIdx.x * blockDim.x + threadIdx.x;
    if (i == 0) g_is64 = (((const long long*)dst1)[15] == 1LL) ? 1 : 0;

    if (i < 256LL * 3 * K1P) {  // W1t
        int n = (int)(i / (3 * K1P)), kk = (int)(i % (3 * K1P));
        int region = kk / K1P, k = kk % K1P;
        float w = 0.f;
        if (k < kFIN) w = Wl1[k * kHID + n];
        else if (k < 2 * kFIN) w = Wr1[(k - kFIN) * kHID + n];
        __nv_bfloat16 hi = __float2bfloat16(w);
        g_W1t[i] = (region < 2) ? hi : __float2bfloat16(w - __bfloat162float(hi));
    }
    if (i < 256LL * 3 * K2P) {  // W2t
        int n = (int)(i / (3 * K2P)), kk = (int)(i % (3 * K2P));
        int region = kk / K2P, k = kk % K2P;
        float w = (k < kHID) ? Wl2[k * kHID + n] : Wr2[(k - kHID) * kHID + n];
        __nv_bfloat16 hi = __float2bfloat16(w);
        g_W2t[i] = (region < 2) ? hi : __float2bfloat16(w - __bfloat162float(hi));
    }
    if (i < 64LL * 3 * K2P) {  // W3t (N padded 47 -> 64)
        int n = (int)(i / (3 * K2P)), kk = (int)(i % (3 * K2P));
        int region = kk / K2P, k = kk % K2P;
        float w = 0.f;
        if (n < kOUT) w = (k < kHID) ? Wl3[k * kOUT + n] : Wr3[(k - kHID) * kOUT + n];
        __nv_bfloat16 hi = __float2bfloat16(w);
        g_W3t[i] = (region < 2) ? hi : __float2bfloat16(w - __bfloat162float(hi));
    }
}

// ---------------- layer-1 aggregation: warp per dst, float4 gathers ----------
__global__ void agg1_kernel(const float* __restrict__ x, const void* __restrict__ src) {
    int gw = (blockIdx.x * blockDim.x + threadIdx.x) >> 5;
    int lane = threadIdx.x & 31;
    if (gw >= kN1) return;
    const int is64 = g_is64;

    long long myidx = 0;
    if (lane < kFAN1) myidx = load_index(src, (long long)gw * kFAN1 + lane, is64);

    const float4* x4 = (const float4*)x;  // 25 float4 per row
    float4 acc = make_float4(0.f, 0.f, 0.f, 0.f);
#pragma unroll
    for (int j = 0; j < kFAN1; ++j) {
        long long r = __shfl_sync(0xffffffffu, myidx, j);
        if (lane < 25) {
            float4 v = __ldg(&x4[r * 25 + lane]);
            acc.x += v.x; acc.y += v.y; acc.z += v.z; acc.w += v.w;
        }
    }
    const float inv = 1.0f / (float)kFAN1;
    __nv_bfloat16* oh = g_A1h + (size_t)gw * K1P;
    __nv_bfloat16* ol = g_A1l + (size_t)gw * K1P;
    if (lane < 25) {
        float4 a = make_float4(acc.x * inv, acc.y * inv, acc.z * inv, acc.w * inv);
        split_store4(oh + 4 * lane, ol + 4 * lane, a);
        float4 d = __ldg(&x4[(size_t)gw * 25 + lane]);
        split_store4(oh + kFIN + 4 * lane, ol + kFIN + 4 * lane, d);
    }
    if (lane < 14) {  // zero-pad cols 200..255
        uint2 z = make_uint2(0u, 0u);
        *(uint2*)(oh + 2 * kFIN + 4 * lane) = z;
        *(uint2*)(ol + 2 * kFIN + 4 * lane) = z;
    }
}

// ---------------- 256-wide aggregation (layers 2,3) --------------------------
template <int FAN>
__global__ void agg256_kernel(const float* __restrict__ h, const void* __restrict__ src,
                              __nv_bfloat16* __restrict__ Ah, __nv_bfloat16* __restrict__ Al,
                              int ndst) {
    int gw = (blockIdx.x * blockDim.x + threadIdx.x) >> 5;
    int lane = threadIdx.x & 31;
    if (gw >= ndst) return;
    const int is64 = g_is64;

    long long myidx = 0;
    if (lane < FAN) myidx = load_index(src, (long long)gw * FAN + lane, is64);

    const float4* h4 = (const float4*)h;  // 64 float4 per row
    float4 a0 = make_float4(0.f, 0.f, 0.f, 0.f);
    float4 a1 = make_float4(0.f, 0.f, 0.f, 0.f);
#pragma unroll
    for (int j = 0; j < FAN; ++j) {
        long long r = __shfl_sync(0xffffffffu, myidx, j);
        float4 v0 = __ldg(&h4[r * 64 + lane]);
        float4 v1 = __ldg(&h4[r * 64 + lane + 32]);
        a0.x += v0.x; a0.y += v0.y; a0.z += v0.z; a0.w += v0.w;
        a1.x += v1.x; a1.y += v1.y; a1.z += v1.z; a1.w += v1.w;
    }
    const float inv = 1.0f / (float)FAN;
    __nv_bfloat16* oh = Ah + (size_t)gw * K2P;
    __nv_bfloat16* ol = Al + (size_t)gw * K2P;
    float4 s0 = make_float4(a0.x * inv, a0.y * inv, a0.z * inv, a0.w * inv);
    float4 s1 = make_float4(a1.x * inv, a1.y * inv, a1.z * inv, a1.w * inv);
    split_store4(oh + 4 * lane, ol + 4 * lane, s0);
    split_store4(oh + 128 + 4 * lane, ol + 128 + 4 * lane, s1);
    float4 d0 = __ldg(&h4[(size_t)gw * 64 + lane]);
    float4 d1 = __ldg(&h4[(size_t)gw * 64 + lane + 32]);
    split_store4(oh + 256 + 4 * lane, ol + 256 + 4 * lane, d0);
    split_store4(oh + 384 + 4 * lane, ol + 384 + 4 * lane, d1);
}

// ---------------- HMMA GEMM: out[M,Ntot] = A'[M,3K] @ Wt[Ntot,3K]^T ----------
// A' = [Ah | Al | Ah] via region-indexed loads. BM=128, BK=32, 256 threads.
// Warp grid 4(m) x 2(n); per warp 32 x BN/2 via m16n8k16 bf16->fp32.
// Smem row stride 40 bf16 (80 B): ldmatrix conflict-free (20*r mod 32 distinct).
template <int BN, int KP, bool RELU, bool FINAL>
__global__ void __launch_bounds__(256) mma_gemm(
    const __nv_bfloat16* __restrict__ Ah, const __nv_bfloat16* __restrict__ Al,
    const __nv_bfloat16* __restrict__ Wt, const float* __restrict__ bias,
    float* __restrict__ out, int ntot) {
    constexpr int BM = 128;
    constexpr int LDS = 40;            // bf16 elems per smem row
    constexpr int NIT = 3 * KP / 32;
    constexpr int NI = BN / 16;        // n8-tiles per warp

    __shared__ __nv_bfloat16 smA[2][BM * LDS];
    __shared__ __nv_bfloat16 smB[2][BN * LDS];
    __shared__ float sbias[BN];

    const int tid = threadIdx.x;
    const int wid = tid >> 5, lane = tid & 31;
    const int wm = wid & 3, wn = wid >> 2;
    const int m0 = wm * 32;
    const int n0 = wn * (BN / 2);
    const size_t rowBase = (size_t)blockIdx.y * BM;
    const int colBase = blockIdx.x * BN;

    if (tid < BN) sbias[tid] = (colBase + tid < ntot) ? bias[colBase + tid] : 0.f;

    const uint32_t sa0 = smem_u32(&smA[0][0]);
    const uint32_t sa1 = smem_u32(&smA[1][0]);
    const uint32_t sb0 = smem_u32(&smB[0][0]);
    const uint32_t sb1 = smem_u32(&smB[1][0]);

    float acc[2][NI][4];
#pragma unroll
    for (int mi = 0; mi < 2; ++mi)
#pragma unroll
        for (int ni = 0; ni < NI; ++ni)
#pragma unroll
            for (int q = 0; q < 4; ++q) acc[mi][ni][q] = 0.f;

    auto load_tile = [&](int it, int buf) {
        const int k0 = it * 32;
        const int region = k0 / KP;
        const int sk = k0 - region * KP;
        const __nv_bfloat16* srcp = ((region == 1) ? Al : Ah) + rowBase * KP + sk;
        const uint32_t abase = buf ? sa1 : sa0;
#pragma unroll
        for (int t = 0; t < 2; ++t) {  // A: 512 16B-chunks
            int c = tid + t * 256;
            int row = c >> 2, kc = c & 3;
            cpasync16(abase + row * (LDS * 2) + kc * 16, srcp + (size_t)row * KP + kc * 8);
        }
        const __nv_bfloat16* wsrc = Wt + (size_t)colBase * (3 * KP) + k0;
        const uint32_t bbase = buf ? sb1 : sb0;
#pragma unroll
        for (int t = 0; t < BN / 64; ++t) {  // B: BN*4 chunks
            int c = tid + t * 256;
            int row = c >> 2, kc = c & 3;
            cpasync16(bbase + row * (LDS * 2) + kc * 16, wsrc + (size_t)row * (3 * KP) + kc * 8);
        }
        asm volatile("cp.async.commit_group;" ::: "memory");
    };

    load_tile(0, 0);
    for (int i = 0; i < NIT; ++i) {
        const int buf = i & 1;
        if (i + 1 < NIT) {
            load_tile(i + 1, buf ^ 1);
            asm volatile("cp.async.wait_group 1;" ::: "memory");
        } else {
            asm volatile("cp.async.wait_group 0;" ::: "memory");
        }
        __syncthreads();

        const uint32_t aA = buf ? sa1 : sa0;
        const uint32_t aB = buf ? sb1 : sb0;
#pragma unroll
        for (int kk = 0; kk < 2; ++kk) {
            uint32_t afr[2][4];
#pragma unroll
            for (int mi = 0; mi < 2; ++mi) {
                uint32_t ad = aA + (uint32_t)((m0 + mi * 16 + (lane & 15)) * (LDS * 2) +
                                              kk * 32 + (lane >> 4) * 16);
                ldm_x4(afr[mi][0], afr[mi][1], afr[mi][2], afr[mi][3], ad);
            }
#pragma unroll
            for (int ni = 0; ni < NI; ++ni) {
                uint32_t b0, b1;
                uint32_t bd = aB + (uint32_t)((n0 + ni * 8 + (lane & 7)) * (LDS * 2) +
                                              kk * 32 + ((lane >> 3) & 1) * 16);
                ldm_x2(b0, b1, bd);
#pragma unroll
                for (int mi = 0; mi < 2; ++mi) mma16816(acc[mi][ni], afr[mi], b0, b1);
            }
        }
        __syncthreads();
    }

    // epilogue
    const int r = lane >> 2;
    const int cp = (lane & 3) * 2;
#pragma unroll
    for (int mi = 0; mi < 2; ++mi) {
#pragma unroll
        for (int ni = 0; ni < NI; ++ni) {
            const int jc = n0 + ni * 8 + cp;            // local col
            const int col = colBase + jc;
            const size_t row0 = rowBase + m0 + mi * 16 + r;
            float v0 = acc[mi][ni][0] + sbias[jc];
            float v1 = acc[mi][ni][1] + sbias[jc + 1];
            float v2 = acc[mi][ni][2] + sbias[jc];
            float v3 = acc[mi][ni][3] + sbias[jc + 1];
            if (RELU) {
                v0 = fmaxf(v0, 0.f); v1 = fmaxf(v1, 0.f);
                v2 = fmaxf(v2, 0.f); v3 = fmaxf(v3, 0.f);
            }
            if (FINAL) {
                if (col < ntot) {
                    out[row0 * ntot + col] = v0;
                    out[(row0 + 8) * ntot + col] = v2;
                }
                if (col + 1 < ntot) {
                    out[row0 * ntot + col + 1] = v1;
                    out[(row0 + 8) * ntot + col + 1] = v3;
                }
            } else {
                *(float2*)(out + row0 * ntot + col) = make_float2(v0, v1);
                *(float2*)(out + (row0 + 8) * ntot + col) = make_float2(v2, v3);
            }
        }
    }
}

// ---------------- log_softmax over 47 cols, warp per row, in place -----------
__global__ void logsoftmax_kernel(float* __restrict__ out) {
    int gw = (blockIdx.x * blockDim.x + threadIdx.x) >> 5;
    int lane = threadIdx.x & 31;
    if (gw >= kN3) return;
    float* row = out + (long long)gw * kOUT;
    float v0 = (lane < kOUT) ? row[lane] : -1e30f;
    float v1 = (lane + 32 < kOUT) ? row[lane + 32] : -1e30f;
    float m = fmaxf(v0, v1);
#pragma unroll
    for (int o = 16; o; o >>= 1) m = fmaxf(m, __shfl_xor_sync(0xffffffffu, m, o));
    float s = 0.f;
    if (lane < kOUT) s += expf(v0 - m);
    if (lane + 32 < kOUT) s += expf(v1 - m);
#pragma unroll
    for (int o = 16; o; o >>= 1) s += __shfl_xor_sync(0xffffffffu, s, o);
    float lse = m + logf(s);
    if (lane < kOUT) row[lane] = v0 - lse;
    if (lane + 32 < kOUT) row[lane + 32] = v1 - lse;
}

// ---------------- launch -----------------------------------------------------
extern "C" void kernel_launch(void* const* d_in, const int* in_sizes, int n_in,
                              void* d_out, int out_size) {
    const float* x   = (const float*)d_in[0];
    const float* Wl1 = (const float*)d_in[1];
    const float* Wr1 = (const float*)d_in[2];
    const float* b1  = (const float*)d_in[3];
    const float* Wl2 = (const float*)d_in[4];
    const float* Wr2 = (const float*)d_in[5];
    const float* b2  = (const float*)d_in[6];
    const float* Wl3 = (const float*)d_in[7];
    const float* Wr3 = (const float*)d_in[8];
    const float* b3  = (const float*)d_in[9];
    const void*  src1 = d_in[10];
    const void*  dst1 = d_in[11];
    const void*  src2 = d_in[12];
    const void*  src3 = d_in[14];
    float* out = (float*)d_out;

    __nv_bfloat16 *A1h, *A1l, *A2h, *A2l, *A3h, *A3l, *W1t, *W2t, *W3t;
    float *h1, *h2;
    cudaGetSymbolAddress((void**)&A1h, g_A1h);
    cudaGetSymbolAddress((void**)&A1l, g_A1l);
    cudaGetSymbolAddress((void**)&A2h, g_A2h);
    cudaGetSymbolAddress((void**)&A2l, g_A2l);
    cudaGetSymbolAddress((void**)&A3h, g_A3h);
    cudaGetSymbolAddress((void**)&A3l, g_A3l);
    cudaGetSymbolAddress((void**)&W1t, g_W1t);
    cudaGetSymbolAddress((void**)&W2t, g_W2t);
    cudaGetSymbolAddress((void**)&W3t, g_W3t);
    cudaGetSymbolAddress((void**)&h1, g_h1);
    cudaGetSymbolAddress((void**)&h2, g_h2);

    // 1. pack weights + index-dtype detect
    pack_weights<<<(256 * 3 * K2P + 255) / 256, 256>>>(Wl1, Wr1, Wl2, Wr2, Wl3, Wr3, dst1);

    // 2. layer 1
    agg1_kernel<<<kN1 / 8, 256>>>(x, src1);
    mma_gemm<128, K1P, true, false><<<dim3(2, kN1 / 128), 256>>>(A1h, A1l, W1t, b1, h1, 256);

    // 3. layer 2
    agg256_kernel<kFAN2><<<kN2 / 8, 256>>>(h1, src2, A2h, A2l, kN2);
    mma_gemm<128, K2P, true, false><<<dim3(2, kN2 / 128), 256>>>(A2h, A2l, W2t, b2, h2, 256);

    // 4. layer 3 -> d_out logits
    agg256_kernel<kFAN3><<<kN3 / 8, 256>>>(h2, src3, A3h, A3l, kN3);
    mma_gemm<64, K2P, false, true><<<dim3(1, kN3 / 128), 256>>>(A3h, A3l, W3t, b3, out, kOUT);

    // 5. log_softmax in place
    logsoftmax_kernel<<<kN3 / 8, 256>>>(out);
}

// round 4
// speedup vs baseline: 3.2956x; 1.6928x over previous
#include <cuda_runtime.h>
#include <cuda_fp16.h>
#include <cstdint>
#include <cstddef>

// ---------------- problem constants ----------------
namespace {
constexpr int kN1 = 67584;
constexpr int kN2 = 6144;
constexpr int kN3 = 1024;
constexpr int kFIN = 100;
constexpr int kHID = 256;
constexpr int kOUT = 47;
constexpr int kFAN1 = 15;
constexpr int kFAN2 = 10;
constexpr int kFAN3 = 5;
constexpr int K1P = 224;   // layer-1 K padded (agg 100 | dst 100 | zeros 24)
constexpr int K2P = 512;   // layer-2/3 K (agg 256 | dst 256)
}  // namespace

// ---------------- scratch (device globals) ----------------------------------
__device__ __half g_A1[(size_t)kN1 * K1P];
__device__ __half g_h1[(size_t)kN1 * kHID];
__device__ __half g_A2[(size_t)kN2 * K2P];
__device__ __half g_h2[(size_t)kN2 * kHID];
__device__ __half g_A3[(size_t)kN3 * K2P];
__device__ __half g_W1t[(size_t)256 * K1P];   // [N][K], transposed
__device__ __half g_W2t[(size_t)256 * K2P];
__device__ __half g_W3t[(size_t)64  * K2P];
__device__ int g_is64;

// ---------------- PTX helpers ------------------------------------------------
__device__ __forceinline__ uint32_t smem_u32(const void* p) {
    uint32_t a;
    asm("{ .reg .u64 t; cvta.to.shared.u64 t, %1; cvt.u32.u64 %0, t; }" : "=r"(a) : "l"(p));
    return a;
}
__device__ __forceinline__ void cpasync16(uint32_t saddr, const void* g) {
    asm volatile("cp.async.cg.shared.global [%0], [%1], 16;" :: "r"(saddr), "l"(g) : "memory");
}
__device__ __forceinline__ void ldm_x4(uint32_t& r0, uint32_t& r1, uint32_t& r2, uint32_t& r3,
                                       uint32_t addr) {
    asm volatile("ldmatrix.sync.aligned.m8n8.x4.shared.b16 {%0,%1,%2,%3}, [%4];"
                 : "=r"(r0), "=r"(r1), "=r"(r2), "=r"(r3) : "r"(addr));
}
__device__ __forceinline__ void ldm_x2(uint32_t& r0, uint32_t& r1, uint32_t addr) {
    asm volatile("ldmatrix.sync.aligned.m8n8.x2.shared.b16 {%0,%1}, [%2];"
                 : "=r"(r0), "=r"(r1) : "r"(addr));
}
__device__ __forceinline__ void mma16816(float* c, const uint32_t* a, uint32_t b0, uint32_t b1) {
    asm volatile(
        "mma.sync.aligned.m16n8k16.row.col.f32.f16.f16.f32 "
        "{%0,%1,%2,%3}, {%4,%5,%6,%7}, {%8,%9}, {%0,%1,%2,%3};"
        : "+f"(c[0]), "+f"(c[1]), "+f"(c[2]), "+f"(c[3])
        : "r"(a[0]), "r"(a[1]), "r"(a[2]), "r"(a[3]), "r"(b0), "r"(b1));
}
__device__ __forceinline__ long long load_index(const void* p, long long i, int is64) {
    return is64 ? ((const long long*)p)[i] : (long long)((const int*)p)[i];
}

// ---------------- pack weights (fp16, transposed [N][K]) ---------------------
__global__ void pack_weights(const float* __restrict__ Wl1, const float* __restrict__ Wr1,
                             const float* __restrict__ Wl2, const float* __restrict__ Wr2,
                             const float* __restrict__ Wl3, const float* __restrict__ Wr3,
                             const void* __restrict__ dst1) {
    int i = blockIdx.x * blockDim.x + threadIdx.x;
    if (i == 0) g_is64 = (((const long long*)dst1)[15] == 1LL) ? 1 : 0;

    if (i < 256 * K1P) {  // W1t
        int n = i / K1P, k = i % K1P;
        float w = 0.f;
        if (k < kFIN) w = Wl1[k * kHID + n];
        else if (k < 2 * kFIN) w = Wr1[(k - kFIN) * kHID + n];
        g_W1t[i] = __float2half_rn(w);
    }
    if (i < 256 * K2P) {  // W2t
        int n = i / K2P, k = i % K2P;
        float w = (k < kHID) ? Wl2[k * kHID + n] : Wr2[(k - kHID) * kHID + n];
        g_W2t[i] = __float2half_rn(w);
    }
    if (i < 64 * K2P) {  // W3t (N padded 47 -> 64)
        int n = i / K2P, k = i % K2P;
        float w = 0.f;
        if (n < kOUT) w = (k < kHID) ? Wl3[k * kOUT + n] : Wr3[(k - kHID) * kOUT + n];
        g_W3t[i] = __float2half_rn(w);
    }
}

// ---------------- layer-1 aggregation: warp per dst, float4 gathers ----------
__global__ void agg1_kernel(const float* __restrict__ x, const void* __restrict__ src) {
    int gw = (blockIdx.x * blockDim.x + threadIdx.x) >> 5;
    int lane = threadIdx.x & 31;
    if (gw >= kN1) return;
    const int is64 = g_is64;

    long long myidx = 0;
    if (lane < kFAN1) myidx = load_index(src, (long long)gw * kFAN1 + lane, is64);

    const float4* x4 = (const float4*)x;  // 25 float4 per row
    float4 acc = make_float4(0.f, 0.f, 0.f, 0.f);
#pragma unroll
    for (int j = 0; j < kFAN1; ++j) {
        long long r = __shfl_sync(0xffffffffu, myidx, j);
        if (lane < 25) {
            float4 v = __ldg(&x4[r * 25 + lane]);
            acc.x += v.x; acc.y += v.y; acc.z += v.z; acc.w += v.w;
        }
    }
    const float inv = 1.0f / (float)kFAN1;
    __half* o = g_A1 + (size_t)gw * K1P;
    if (lane < 25) {
        __half2 p0 = __floats2half2_rn(acc.x * inv, acc.y * inv);
        __half2 p1 = __floats2half2_rn(acc.z * inv, acc.w * inv);
        *(__half2*)(o + 4 * lane) = p0;
        *(__half2*)(o + 4 * lane + 2) = p1;
        float4 d = __ldg(&x4[(size_t)gw * 25 + lane]);
        *(__half2*)(o + kFIN + 4 * lane) = __floats2half2_rn(d.x, d.y);
        *(__half2*)(o + kFIN + 4 * lane + 2) = __floats2half2_rn(d.z, d.w);
    }
    if (lane < 6) {  // zero-pad cols 200..223
        *(uint2*)(o + 200 + 4 * lane) = make_uint2(0u, 0u);
    }
}

// ---------------- 256-wide fp16 aggregation (layers 2,3) ---------------------
// h rows: 256 fp16 = 512 B = 32 uint4; lane handles 8 features.
template <int FAN>
__global__ void agg256_kernel(const __half* __restrict__ h, const void* __restrict__ src,
                              __half* __restrict__ A, int ndst) {
    int gw = (blockIdx.x * blockDim.x + threadIdx.x) >> 5;
    int lane = threadIdx.x & 31;
    if (gw >= ndst) return;
    const int is64 = g_is64;

    long long myidx = 0;
    if (lane < FAN) myidx = load_index(src, (long long)gw * FAN + lane, is64);

    const uint4* h4 = (const uint4*)h;  // 32 uint4 per row
    float acc[8];
#pragma unroll
    for (int t = 0; t < 8; ++t) acc[t] = 0.f;

#pragma unroll
    for (int j = 0; j < FAN; ++j) {
        long long r = __shfl_sync(0xffffffffu, myidx, j);
        uint4 v = __ldg(&h4[r * 32 + lane]);
        const __half2* hv = (const __half2*)&v;
#pragma unroll
        for (int q = 0; q < 4; ++q) {
            float2 f = __half22float2(hv[q]);
            acc[2 * q] += f.x;
            acc[2 * q + 1] += f.y;
        }
    }
    const float inv = 1.0f / (float)FAN;
    uint4 outv;
    __half2* ho = (__half2*)&outv;
#pragma unroll
    for (int q = 0; q < 4; ++q)
        ho[q] = __floats2half2_rn(acc[2 * q] * inv, acc[2 * q + 1] * inv);
    uint4* o = (uint4*)(A + (size_t)gw * K2P);
    o[lane] = outv;                                   // agg half (cols 0..255)
    o[32 + lane] = __ldg(&h4[(size_t)gw * 32 + lane]);  // dst half (verbatim copy)
}

// ---------------- HMMA GEMM: out[M,Ntot] = A[M,K] @ Wt[Ntot,K]^T -------------
// BM=128, BK=32, 256 threads. Warp grid 4(m) x 2(n); warp tile 32 x BN/2 via
// m16n8k16 fp16->fp32. Smem row stride 40 fp16 (80 B), ldmatrix conflict-free.
template <int BN, int KP, bool RELU, bool FINAL>
__global__ void __launch_bounds__(256) mma_gemm(
    const __half* __restrict__ Ap, const __half* __restrict__ Wt,
    const float* __restrict__ bias, void* __restrict__ outv, int ntot) {
    constexpr int BM = 128;
    constexpr int LDS = 40;
    constexpr int NIT = KP / 32;
    constexpr int NI = BN / 16;

    __shared__ __half smA[2][BM * LDS];
    __shared__ __half smB[2][BN * LDS];
    __shared__ float sbias[BN];

    const int tid = threadIdx.x;
    const int wid = tid >> 5, lane = tid & 31;
    const int wm = wid & 3, wn = wid >> 2;
    const int m0 = wm * 32;
    const int n0 = wn * (BN / 2);
    const size_t rowBase = (size_t)blockIdx.y * BM;
    const int colBase = blockIdx.x * BN;

    if (tid < BN) sbias[tid] = (colBase + tid < ntot) ? bias[colBase + tid] : 0.f;

    const uint32_t sa0 = smem_u32(&smA[0][0]);
    const uint32_t sa1 = smem_u32(&smA[1][0]);
    const uint32_t sb0 = smem_u32(&smB[0][0]);
    const uint32_t sb1 = smem_u32(&smB[1][0]);

    float acc[2][NI][4];
#pragma unroll
    for (int mi = 0; mi < 2; ++mi)
#pragma unroll
        for (int ni = 0; ni < NI; ++ni)
#pragma unroll
            for (int q = 0; q < 4; ++q) acc[mi][ni][q] = 0.f;

    auto load_tile = [&](int it, int buf) {
        const int k0 = it * 32;
        const __half* srcp = Ap + rowBase * KP + k0;
        const uint32_t abase = buf ? sa1 : sa0;
#pragma unroll
        for (int t = 0; t < 2; ++t) {  // A: 512 16B-chunks
            int c = tid + t * 256;
            int row = c >> 2, kc = c & 3;
            cpasync16(abase + row * (LDS * 2) + kc * 16, srcp + (size_t)row * KP + kc * 8);
        }
        const __half* wsrc = Wt + (size_t)colBase * KP + k0;
        const uint32_t bbase = buf ? sb1 : sb0;
#pragma unroll
        for (int t = 0; t < BN / 64; ++t) {  // B: BN*4 chunks
            int c = tid + t * 256;
            int row = c >> 2, kc = c & 3;
            cpasync16(bbase + row * (LDS * 2) + kc * 16, wsrc + (size_t)row * KP + kc * 8);
        }
        asm volatile("cp.async.commit_group;" ::: "memory");
    };

    load_tile(0, 0);
    for (int i = 0; i < NIT; ++i) {
        const int buf = i & 1;
        if (i + 1 < NIT) {
            load_tile(i + 1, buf ^ 1);
            asm volatile("cp.async.wait_group 1;" ::: "memory");
        } else {
            asm volatile("cp.async.wait_group 0;" ::: "memory");
        }
        __syncthreads();

        const uint32_t aA = buf ? sa1 : sa0;
        const uint32_t aB = buf ? sb1 : sb0;
#pragma unroll
        for (int kk = 0; kk < 2; ++kk) {
            uint32_t afr[2][4];
#pragma unroll
            for (int mi = 0; mi < 2; ++mi) {
                uint32_t ad = aA + (uint32_t)((m0 + mi * 16 + (lane & 15)) * (LDS * 2) +
                                              kk * 32 + (lane >> 4) * 16);
                ldm_x4(afr[mi][0], afr[mi][1], afr[mi][2], afr[mi][3], ad);
            }
#pragma unroll
            for (int ni = 0; ni < NI; ++ni) {
                uint32_t b0, b1;
                uint32_t bd = aB + (uint32_t)((n0 + ni * 8 + (lane & 7)) * (LDS * 2) +
                                              kk * 32 + ((lane >> 3) & 1) * 16);
                ldm_x2(b0, b1, bd);
#pragma unroll
                for (int mi = 0; mi < 2; ++mi) mma16816(acc[mi][ni], afr[mi], b0, b1);
            }
        }
        __syncthreads();
    }

    // epilogue
    const int r = lane >> 2;
    const int cp = (lane & 3) * 2;
#pragma unroll
    for (int mi = 0; mi < 2; ++mi) {
#pragma unroll
        for (int ni = 0; ni < NI; ++ni) {
            const int jc = n0 + ni * 8 + cp;
            const int col = colBase + jc;
            const size_t row0 = rowBase + m0 + mi * 16 + r;
            float v0 = acc[mi][ni][0] + sbias[jc];
            float v1 = acc[mi][ni][1] + sbias[jc + 1];
            float v2 = acc[mi][ni][2] + sbias[jc];
            float v3 = acc[mi][ni][3] + sbias[jc + 1];
            if (RELU) {
                v0 = fmaxf(v0, 0.f); v1 = fmaxf(v1, 0.f);
                v2 = fmaxf(v2, 0.f); v3 = fmaxf(v3, 0.f);
            }
            if (FINAL) {
                float* out = (float*)outv;
                if (col < ntot) {
                    out[row0 * ntot + col] = v0;
                    out[(row0 + 8) * ntot + col] = v2;
                }
                if (col + 1 < ntot) {
                    out[row0 * ntot + col + 1] = v1;
                    out[(row0 + 8) * ntot + col + 1] = v3;
                }
            } else {
                __half* out = (__half*)outv;
                *(__half2*)(out + row0 * ntot + col) = __floats2half2_rn(v0, v1);
                *(__half2*)(out + (row0 + 8) * ntot + col) = __floats2half2_rn(v2, v3);
            }
        }
    }
}

// ---------------- log_softmax over 47 cols, warp per row, in place -----------
__global__ void logsoftmax_kernel(float* __restrict__ out) {
    int gw = (blockIdx.x * blockDim.x + threadIdx.x) >> 5;
    int lane = threadIdx.x & 31;
    if (gw >= kN3) return;
    float* row = out + (long long)gw * kOUT;
    float v0 = (lane < kOUT) ? row[lane] : -1e30f;
    float v1 = (lane + 32 < kOUT) ? row[lane + 32] : -1e30f;
    float m = fmaxf(v0, v1);
#pragma unroll
    for (int o = 16; o; o >>= 1) m = fmaxf(m, __shfl_xor_sync(0xffffffffu, m, o));
    float s = 0.f;
    if (lane < kOUT) s += expf(v0 - m);
    if (lane + 32 < kOUT) s += expf(v1 - m);
#pragma unroll
    for (int o = 16; o; o >>= 1) s += __shfl_xor_sync(0xffffffffu, s, o);
    float lse = m + logf(s);
    if (lane < kOUT) row[lane] = v0 - lse;
    if (lane + 32 < kOUT) row[lane + 32] = v1 - lse;
}

// ---------------- launch -----------------------------------------------------
extern "C" void kernel_launch(void* const* d_in, const int* in_sizes, int n_in,
                              void* d_out, int out_size) {
    const float* x   = (const float*)d_in[0];
    const float* Wl1 = (const float*)d_in[1];
    const float* Wr1 = (const float*)d_in[2];
    const float* b1  = (const float*)d_in[3];
    const float* Wl2 = (const float*)d_in[4];
    const float* Wr2 = (const float*)d_in[5];
    const float* b2  = (const float*)d_in[6];
    const float* Wl3 = (const float*)d_in[7];
    const float* Wr3 = (const float*)d_in[8];
    const float* b3  = (const float*)d_in[9];
    const void*  src1 = d_in[10];
    const void*  dst1 = d_in[11];
    const void*  src2 = d_in[12];
    const void*  src3 = d_in[14];
    float* out = (float*)d_out;

    __half *A1, *A2, *A3, *W1t, *W2t, *W3t, *h1, *h2;
    cudaGetSymbolAddress((void**)&A1, g_A1);
    cudaGetSymbolAddress((void**)&A2, g_A2);
    cudaGetSymbolAddress((void**)&A3, g_A3);
    cudaGetSymbolAddress((void**)&W1t, g_W1t);
    cudaGetSymbolAddress((void**)&W2t, g_W2t);
    cudaGetSymbolAddress((void**)&W3t, g_W3t);
    cudaGetSymbolAddress((void**)&h1, g_h1);
    cudaGetSymbolAddress((void**)&h2, g_h2);

    // 1. pack weights + index-dtype detect
    pack_weights<<<(256 * K2P + 255) / 256, 256>>>(Wl1, Wr1, Wl2, Wr2, Wl3, Wr3, dst1);

    // 2. layer 1
    agg1_kernel<<<kN1 / 8, 256>>>(x, src1);
    mma_gemm<128, K1P, true, false><<<dim3(2, kN1 / 128), 256>>>(A1, W1t, b1, h1, 256);

    // 3. layer 2
    agg256_kernel<kFAN2><<<kN2 / 8, 256>>>(h1, src2, A2, kN2);
    mma_gemm<128, K2P, true, false><<<dim3(2, kN2 / 128), 256>>>(A2, W2t, b2, h2, 256);

    // 4. layer 3 -> d_out logits
    agg256_kernel<kFAN3><<<kN3 / 8, 256>>>(h2, src3, A3, kN3);
    mma_gemm<64, K2P, false, true><<<dim3(1, kN3 / 128), 256>>>(A3, W3t, b3, out, kOUT);

    // 5. log_softmax in place
    logsoftmax_kernel<<<kN3 / 8, 256>>>(out);
}